// round 14
// baseline (speedup 1.0000x reference)
#include <cuda_runtime.h>
#include <cstdint>

// Problem constants (fixed shapes for this problem instance)
#define BS 4
#define C  64
#define H  160
#define W  160
#define HW (H * W)
#define KK 25          // 5x5 taps
#define CH_SPLIT 2
#define CH_PER (C / CH_SPLIT)   // 32 channels per block
#define XQ 8           // x-quads (of 4 px) per block
#define YB 16          // rows per block (4 warps x 4 rows)
#define NSTG 4         // cp.async pipeline depth
#define SROW 40        // staged floats per row: cols xb-4 .. xb+35
#define SROWB (SROW * 4)      // 160 B
#define STAGEB (8 * SROWB)    // 1280 B per stage (8 rows)
#define NSLOT 80              // 16B copy slots per stage (8 rows x 10 quads)
#define STRIP_PER_BZ (2 * CH_PER * H)   // 10240 strip outputs per (b, chalf)
#define STRIP_PER_BLK 205               // ceil(10240 / 50)

typedef unsigned long long u64;

__device__ __forceinline__ u64 pk2(float lo, float hi) {
    u64 r; asm("mov.b64 %0, {%1, %2};" : "=l"(r) : "f"(lo), "f"(hi)); return r;
}
__device__ __forceinline__ void up2(u64 v, float &lo, float &hi) {
    asm("mov.b64 {%0, %1}, %2;" : "=f"(lo), "=f"(hi) : "l"(v));
}
__device__ __forceinline__ void fma2(u64 &acc, u64 a, u64 b) {
    asm("fma.rn.f32x2 %0, %1, %2, %0;" : "+l"(acc) : "l"(a), "l"(b));
}
__device__ __forceinline__ u64 add2(u64 a, u64 b) {
    u64 r; asm("add.rn.f32x2 %0, %1, %2;" : "=l"(r) : "l"(a), "l"(b)); return r;
}
__device__ __forceinline__ void cpa16(uint32_t s, const float* g) {
    asm volatile("cp.async.cg.shared.global [%0], [%1], 16;" :: "r"(s), "l"(g));
}
__device__ __forceinline__ float4 lds128(uint32_t a) {
    float4 v;
    asm("ld.shared.v4.f32 {%0,%1,%2,%3}, [%4];"
        : "=f"(v.x), "=f"(v.y), "=f"(v.z), "=f"(v.w) : "r"(a));
    return v;
}
__device__ __forceinline__ int iclamp(int v, int lo, int hi) {
    return v < lo ? lo : (v > hi ? hi : v);
}

// Scalar strip output: out[b, cc, y, x] for x in {0,1} (dilation 1).
__device__ __forceinline__ void strip_one(const float* __restrict__ fm,
                                          const float* __restrict__ kern,
                                          float* __restrict__ out,
                                          int b, int cc, int y, int x)
{
    const float* kb0 = kern + ((size_t)b * KK * H + y) * W + x;
    const float* fc  = fm + ((size_t)(b * C + cc)) * HW;
    float acc = 0.f;
    #pragma unroll
    for (int i = 0; i < 5; i++) {
        const int yy = y + i - 2;
        if (yy < 0 || yy >= H) continue;
        const float* rp = fc + yy * W;
        #pragma unroll
        for (int j = 0; j < 5; j++) {
            const int xx = x + j - 2;
            if (xx < 0 || xx >= W) continue;
            acc += kb0[(size_t)(KK - 1 - (i * 5 + j)) * HW] * rp[xx];
        }
    }
    out[((size_t)(b * C + cc) * H + y) * W + x] = acc;
}

__global__ void __launch_bounds__(XQ * YB, 3)
kconv_kernel(const float* __restrict__ fm, const float* __restrict__ kern,
             const int* __restrict__ dil, float* __restrict__ out)
{
    // 4 warps x 4 stages x 8 rows x 40 floats = 20480 B
    __shared__ __align__(16) float sbuf[4 * NSTG * 8 * SROW];

    const int tx = threadIdx.x;
    const int ty = threadIdx.y;
    const int bz = blockIdx.z;
    const int b  = bz >> 1;
    const int c0 = (bz & 1) * CH_PER;
    const int y  = blockIdx.y * YB + ty;
    const int d  = dil ? dil[0] : 1;

    if (d == 1) {
        // Shifted tiling: this thread owns pixels x0 .. x0+3 with x0 = 32*bx + 4*tx + 2.
        // (pixels 0,1 handled by the strip epilogue; pixels >= W are phantom)
        const int x0 = blockIdx.x * 32 + tx * 4 + 2;
        const bool phantom = (x0 + 2 >= W);    // px x0+2, x0+3 do not exist

        // ---- Weights (flipped tap order), 2 x LDG.64 per tap (x0 is 8B-aligned).
        u64 w01[KK], w23[KK];
        {
            const float* kb = kern + ((size_t)b * KK * H + y) * W + x0;
            #pragma unroll
            for (int t = 0; t < KK; t++) {
                const float2 wa = *reinterpret_cast<const float2*>(
                    kb + (size_t)(KK - 1 - t) * HW);
                w01[t] = pk2(wa.x, wa.y);
                w23[t] = 0ull;
            }
            if (!phantom) {
                #pragma unroll
                for (int t = 0; t < KK; t++) {
                    const float2 wb = *reinterpret_cast<const float2*>(
                        kb + (size_t)(KK - 1 - t) * HW + 2);
                    w23[t] = pk2(wb.x, wb.y);
                }
            }
        }

        // ---- Fold boundary handling into the weights ONCE per thread. ----
        #pragma unroll
        for (int i = 0; i < 5; i++) {
            const int yy = y + i - 2;
            const bool rok = (yy >= 0) && (yy < H);
            #pragma unroll
            for (int j = 0; j < 5; j++) {
                float a0, a1, a2, a3;
                up2(w01[i * 5 + j], a0, a1);
                up2(w23[i * 5 + j], a2, a3);
                if (!rok || x0 + 0 + j - 2 < 0 || x0 + 0 + j - 2 >= W) a0 = 0.f;
                if (!rok || x0 + 1 + j - 2 < 0 || x0 + 1 + j - 2 >= W) a1 = 0.f;
                if (!rok || x0 + 2 + j - 2 < 0 || x0 + 2 + j - 2 >= W) a2 = 0.f;
                if (!rok || x0 + 3 + j - 2 < 0 || x0 + 3 + j - 2 >= W) a3 = 0.f;
                w01[i * 5 + j] = pk2(a0, a1);
                w23[i * 5 + j] = pk2(a2, a3);
            }
        }

        // ---- Per-warp cp.async staging (16B .cg granules, proven in R11):
        // warp w covers rows yw0..yw0+3; staged rows yw0-2..yw0+5 (clamped),
        // cols xb-4..xb+35 (clamped; mis-staged values get zero weights).
        // Thread's window v0..v9 = cols x0-4..x0+5 -> staged float idx
        // 4tx+2..4tx+11, so v2 is 16B-aligned -> TWO conflict-free LDS.128/row.
        const int lane = tx + (ty & 3) * 8;    // == tid % 32
        const int w    = ty >> 2;
        const int tyw  = ty & 3;
        const int xb   = blockIdx.x * 32;
        const int yw0  = blockIdx.y * YB + w * 4;

        const uint32_t sbase =
            (uint32_t)__cvta_generic_to_shared(sbuf) + (uint32_t)(w * NSTG * STAGEB);

        int gof[3]; uint32_t sof[3];
        #pragma unroll
        for (int k = 0; k < 3; k++) {
            const int slot = lane + 32 * k;
            const int r  = (slot < NSLOT) ? slot / 10 : 0;
            const int q  = (slot < NSLOT) ? slot % 10 : 0;
            const int rg = iclamp(yw0 - 2 + r, 0, H - 1);
            const int cg = iclamp(xb - 4 + q * 4, 0, W - 4);
            gof[k] = rg * W + cg;
            sof[k] = sbase + (uint32_t)(r * SROWB + q * 16);
        }
        const bool have3 = (lane < NSLOT - 64);   // lane < 16

        const float* fb = fm  + (size_t)(b * C + c0) * HW;
        float*       ob = out + ((size_t)(b * C + c0) * H + y) * W + x0;

        // Prologue: prefetch channels 0..NSTG-1.
        #pragma unroll
        for (int p = 0; p < NSTG; p++) {
            const float* fc = fb + (size_t)p * HW;
            const uint32_t so = (uint32_t)(p * STAGEB);
            cpa16(sof[0] + so, fc + gof[0]);
            cpa16(sof[1] + so, fc + gof[1]);
            if (have3) cpa16(sof[2] + so, fc + gof[2]);
            asm volatile("cp.async.commit_group;");
        }

        // v2 of this thread at byte tx*16 + 16 within its tap-row.
        const uint32_t lbase = sbase + (uint32_t)(tyw * SROWB + tx * 16 + 16);
        int s = 0;

        #pragma unroll 1
        for (int c = 0; c < CH_PER; c++) {
            asm volatile("cp.async.wait_group %0;" :: "n"(NSTG - 1));
            __syncwarp();

            const uint32_t lb = lbase + (uint32_t)(s * STAGEB);
            u64 accA = 0ull, accB = 0ull, accC = 0ull, accD = 0ull;
            #pragma unroll
            for (int i = 0; i < 5; i++) {
                const uint32_t ra = lb + (uint32_t)(i * SROWB);
                const float4 f25 = lds128(ra);        // v2 v3 v4 v5
                const float4 f69 = lds128(ra + 16);   // v6 v7 v8 v9
                const u64 P23 = pk2(f25.x, f25.y);
                const u64 P45 = pk2(f25.z, f25.w);
                const u64 P67 = pk2(f69.x, f69.y);
                const u64 P89 = pk2(f69.z, f69.w);
                const u64 P34 = pk2(f25.y, f25.z);
                const u64 P56 = pk2(f25.w, f69.x);
                const u64 P78 = pk2(f69.y, f69.z);
                const int t = i * 5;
                fma2(accA, P23, w01[t + 0]);
                fma2(accB, P34, w01[t + 1]);
                fma2(accA, P45, w01[t + 2]);
                fma2(accB, P56, w01[t + 3]);
                fma2(accA, P67, w01[t + 4]);
                fma2(accC, P45, w23[t + 0]);
                fma2(accD, P56, w23[t + 1]);
                fma2(accC, P67, w23[t + 2]);
                fma2(accD, P78, w23[t + 3]);
                fma2(accC, P89, w23[t + 4]);
            }
            const u64 s01 = add2(accA, accB);
            float2 o01;
            up2(s01, o01.x, o01.y);
            *reinterpret_cast<float2*>(ob) = o01;            // px x0, x0+1
            if (!phantom) {
                const u64 s23 = add2(accC, accD);
                float2 o23;
                up2(s23, o23.x, o23.y);
                *reinterpret_cast<float2*>(ob + 2) = o23;    // px x0+2, x0+3
            }
            ob += HW;

            // Prefetch channel c+NSTG into the stage just consumed.
            // Safe WAR: in-order warp issue means the FMAs consuming this stage's
            // LDS data issued (operands ready) before these LDGSTS issue.
            if (c + NSTG < CH_PER) {
                const float* fc = fb + (size_t)(c + NSTG) * HW;
                const uint32_t so = (uint32_t)(s * STAGEB);
                cpa16(sof[0] + so, fc + gof[0]);
                cpa16(sof[1] + so, fc + gof[1]);
                if (have3) cpa16(sof[2] + so, fc + gof[2]);
            }
            asm volatile("cp.async.commit_group;");   // empty group ok near the tail

            s = (s == NSTG - 1) ? 0 : s + 1;
        }

        // ---- Strip epilogue: pixels x in {0,1} (~2 outputs per thread). ----
        // The 50 blocks sharing this bz split the 10240 strip outputs.
        {
            const int L   = blockIdx.x * 10 + blockIdx.y;      // 0..49
            const int tid = ty * XQ + tx;                      // 0..127
            const int base = L * STRIP_PER_BLK;
            const int lim  = min(base + STRIP_PER_BLK, STRIP_PER_BZ);
            #pragma unroll
            for (int rnd = 0; rnd < 2; rnd++) {
                const int o = base + rnd * 128 + tid;
                if (o < lim) {
                    const int cc = c0 + o / (2 * H);
                    const int r  = o % (2 * H);
                    strip_one(fm, kern, out, b, cc, r >> 1, r & 1);
                }
            }
        }
    } else {
        // ---- Generic dilation path (correctness fallback; not the benched case).
        // Unshifted tiling covers ALL pixels (no strip needed for d != 1).
        const int x0 = (blockIdx.x * XQ + tx) * 4;
        float wq0[KK], wq1[KK], wq2[KK], wq3[KK];
        {
            const float* kb = kern + ((size_t)b * KK * H + y) * W + x0;
            #pragma unroll
            for (int t = 0; t < KK; t++) {
                const float4 wq =
                    *reinterpret_cast<const float4*>(kb + (size_t)(KK - 1 - t) * HW);
                wq0[t] = wq.x; wq1[t] = wq.y; wq2[t] = wq.z; wq3[t] = wq.w;
            }
        }
        #pragma unroll 1
        for (int c = 0; c < CH_PER; c++) {
            float a0 = 0.f, a1 = 0.f, a2 = 0.f, a3 = 0.f;
            const float* fc = fm + (size_t)((b * C + c0 + c) * H) * W;
            #pragma unroll
            for (int i = 0; i < 5; i++) {
                const int yy = y + (i - 2) * d;
                if (yy < 0 || yy >= H) continue;
                const float* rp = fc + yy * W;
                #pragma unroll
                for (int j = 0; j < 5; j++) {
                    const int t = i * 5 + j;
                    const int xb2 = x0 + (j - 2) * d;
                    a0 += wq0[t] * ((xb2     >= 0 && xb2     < W) ? rp[xb2    ] : 0.f);
                    a1 += wq1[t] * ((xb2 + 1 >= 0 && xb2 + 1 < W) ? rp[xb2 + 1] : 0.f);
                    a2 += wq2[t] * ((xb2 + 2 >= 0 && xb2 + 2 < W) ? rp[xb2 + 2] : 0.f);
                    a3 += wq3[t] * ((xb2 + 3 >= 0 && xb2 + 3 < W) ? rp[xb2 + 3] : 0.f);
                }
            }
            float* op = out + (size_t)((b * C + c0 + c) * H + y) * W + x0;
            op[0] = a0; op[1] = a1; op[2] = a2; op[3] = a3;
        }
    }
}

extern "C" void kernel_launch(void* const* d_in, const int* in_sizes, int n_in,
                              void* d_out, int out_size) {
    const float* fm   = (const float*)d_in[0];
    const float* kern = (const float*)d_in[1];
    const int*   dil  = (n_in > 2) ? (const int*)d_in[2] : nullptr;
    float*       out  = (float*)d_out;

    dim3 blk(XQ, YB, 1);                          // 128 threads, 4 warps
    dim3 grd(W / 4 / XQ, H / YB, BS * CH_SPLIT);  // (5, 10, 8) = 400 blocks, 1 wave
    kconv_kernel<<<grd, blk>>>(fm, kern, dil, out);
}

// round 16
// speedup vs baseline: 1.0437x; 1.0437x over previous
#include <cuda_runtime.h>
#include <cstdint>

// Problem constants (fixed shapes for this problem instance)
#define BS 4
#define C  64
#define H  160
#define W  160
#define HW (H * W)
#define KK 25          // 5x5 taps
#define CH_SPLIT 2
#define CH_PER (C / CH_SPLIT)   // 32 channels per block
#define XQ 8           // x-quads (of 4 px) per block
#define YB 16          // rows per block (4 warps x 4 rows)
#define NSTG 4         // cp.async pipeline depth
#define SROW 40        // staged floats per row: cols xb-4 .. xb+35
#define SROWB (SROW * 4)      // 160 B
#define STAGEB (8 * SROWB)    // 1280 B per stage (8 rows)
#define NSLOT 80              // 16B copy slots per stage (8 rows x 10 quads)
#define SYX 7                 // strip (y,x) pairs handled per block (50*7 >= 320)

typedef unsigned long long u64;

__device__ __forceinline__ u64 pk2(float lo, float hi) {
    u64 r; asm("mov.b64 %0, {%1, %2};" : "=l"(r) : "f"(lo), "f"(hi)); return r;
}
__device__ __forceinline__ void up2(u64 v, float &lo, float &hi) {
    asm("mov.b64 {%0, %1}, %2;" : "=f"(lo), "=f"(hi) : "l"(v));
}
__device__ __forceinline__ void fma2(u64 &acc, u64 a, u64 b) {
    asm("fma.rn.f32x2 %0, %1, %2, %0;" : "+l"(acc) : "l"(a), "l"(b));
}
__device__ __forceinline__ u64 add2(u64 a, u64 b) {
    u64 r; asm("add.rn.f32x2 %0, %1, %2;" : "=l"(r) : "l"(a), "l"(b)); return r;
}
__device__ __forceinline__ void cpa16(uint32_t s, const float* g) {
    asm volatile("cp.async.cg.shared.global [%0], [%1], 16;" :: "r"(s), "l"(g));
}
__device__ __forceinline__ float4 lds128(uint32_t a) {
    float4 v;
    asm("ld.shared.v4.f32 {%0,%1,%2,%3}, [%4];"
        : "=f"(v.x), "=f"(v.y), "=f"(v.z), "=f"(v.w) : "r"(a));
    return v;
}
__device__ __forceinline__ int iclamp(int v, int lo, int hi) {
    return v < lo ? lo : (v > hi ? hi : v);
}

__global__ void __launch_bounds__(XQ * YB, 3)
kconv_kernel(const float* __restrict__ fm, const float* __restrict__ kern,
             const int* __restrict__ dil, float* __restrict__ out)
{
    // staging: 4 warps x 4 stages x 8 rows x 40 floats = 20480 B
    __shared__ __align__(16) float sbuf[4 * NSTG * 8 * SROW];
    // strip weights: 7 (y,x) pairs x 25 taps (boundary-folded)
    __shared__ float swt[SYX * KK];

    const int tx = threadIdx.x;
    const int ty = threadIdx.y;
    const int bz = blockIdx.z;
    const int b  = bz >> 1;
    const int c0 = (bz & 1) * CH_PER;
    const int y  = blockIdx.y * YB + ty;
    const int d  = dil ? dil[0] : 1;

    if (d == 1) {
        // Shifted tiling: thread owns pixels x0 .. x0+3, x0 = 32*bx + 4*tx + 2.
        // Covers px 2..159 (+ phantom 160,161). Pixels 0,1 via in-loop strip work.
        const int x0 = blockIdx.x * 32 + tx * 4 + 2;
        const bool phantom = (x0 + 2 >= W);    // px x0+2, x0+3 do not exist

        // ---- Strip weights -> smem (one time). Block L handles strip (y,x)
        // pairs yx = L*7 .. L*7+6 (yx < 320; y = yx>>1, x = yx&1), folded.
        // NOTE: 175 entries > 128 threads -> strided loop (R15 bug was `if`).
        {
            const int tid = ty * XQ + tx;
            const int L   = blockIdx.x * 10 + blockIdx.y;
            for (int idx = tid; idx < SYX * KK; idx += XQ * YB) {
                const int yxl = idx / KK;
                const int t   = idx % KK;      // tap index (flipped convention)
                const int yxg = L * SYX + yxl;
                float v = 0.f;
                if (yxg < 2 * H) {
                    const int ys = yxg >> 1, xs = yxg & 1;
                    const int i = t / 5, j = t % 5;
                    const int yy = ys + i - 2, xx = xs + j - 2;
                    if (yy >= 0 && yy < H && xx >= 0 && xx < W)
                        v = kern[((size_t)b * KK + (KK - 1 - t)) * HW + ys * W + xs];
                }
                swt[idx] = v;
            }
        }

        // ---- Weights (flipped tap order), 2 x LDG.64 per tap (x0 is 8B-aligned).
        u64 w01[KK], w23[KK];
        {
            const float* kb = kern + ((size_t)b * KK * H + y) * W + x0;
            #pragma unroll
            for (int t = 0; t < KK; t++) {
                const float2 wa = *reinterpret_cast<const float2*>(
                    kb + (size_t)(KK - 1 - t) * HW);
                w01[t] = pk2(wa.x, wa.y);
                w23[t] = 0ull;
            }
            if (!phantom) {
                #pragma unroll
                for (int t = 0; t < KK; t++) {
                    const float2 wb = *reinterpret_cast<const float2*>(
                        kb + (size_t)(KK - 1 - t) * HW + 2);
                    w23[t] = pk2(wb.x, wb.y);
                }
            }
        }

        // ---- Fold boundary handling into the weights ONCE per thread. ----
        #pragma unroll
        for (int i = 0; i < 5; i++) {
            const int yy = y + i - 2;
            const bool rok = (yy >= 0) && (yy < H);
            #pragma unroll
            for (int j = 0; j < 5; j++) {
                float a0, a1, a2, a3;
                up2(w01[i * 5 + j], a0, a1);
                up2(w23[i * 5 + j], a2, a3);
                if (!rok || x0 + 0 + j - 2 < 0 || x0 + 0 + j - 2 >= W) a0 = 0.f;
                if (!rok || x0 + 1 + j - 2 < 0 || x0 + 1 + j - 2 >= W) a1 = 0.f;
                if (!rok || x0 + 2 + j - 2 < 0 || x0 + 2 + j - 2 >= W) a2 = 0.f;
                if (!rok || x0 + 3 + j - 2 < 0 || x0 + 3 + j - 2 >= W) a3 = 0.f;
                w01[i * 5 + j] = pk2(a0, a1);
                w23[i * 5 + j] = pk2(a2, a3);
            }
        }

        // ---- Per-warp cp.async staging (16B .cg): warp w covers rows yw0..yw0+3;
        // staged rows yw0-2..yw0+5 (clamped), cols xb-4..xb+35 (clamped; mis-staged
        // values get zero weights). Window v0..v9 = cols x0-4..x0+5 sits at staged
        // float idx 4tx+2..4tx+11, so v2 is 16B-aligned -> TWO conflict-free
        // LDS.128 per tap-row.
        const int lane = tx + (ty & 3) * 8;    // == tid % 32
        const int w    = ty >> 2;
        const int tyw  = ty & 3;
        const int xb   = blockIdx.x * 32;
        const int yw0  = blockIdx.y * YB + w * 4;

        const uint32_t sbase =
            (uint32_t)__cvta_generic_to_shared(sbuf) + (uint32_t)(w * NSTG * STAGEB);

        int gof[3]; uint32_t sof[3];
        #pragma unroll
        for (int k = 0; k < 3; k++) {
            const int slot = lane + 32 * k;
            const int r  = (slot < NSLOT) ? slot / 10 : 0;
            const int q  = (slot < NSLOT) ? slot % 10 : 0;
            const int rg = iclamp(yw0 - 2 + r, 0, H - 1);
            const int cg = iclamp(xb - 4 + q * 4, 0, W - 4);
            gof[k] = rg * W + cg;
            sof[k] = sbase + (uint32_t)(r * SROWB + q * 16);
        }
        const bool have3 = (lane < NSLOT - 64);   // lane < 16

        const float* fb = fm  + (size_t)(b * C + c0) * HW;
        float*       ob = out + ((size_t)(b * C + c0) * H + y) * W + x0;

        // Prologue: prefetch channels 0..NSTG-1.
        #pragma unroll
        for (int p = 0; p < NSTG; p++) {
            const float* fc = fb + (size_t)p * HW;
            const uint32_t so = (uint32_t)(p * STAGEB);
            cpa16(sof[0] + so, fc + gof[0]);
            cpa16(sof[1] + so, fc + gof[1]);
            if (have3) cpa16(sof[2] + so, fc + gof[2]);
            asm volatile("cp.async.commit_group;");
        }

        __syncthreads();   // strip weights visible before iter-10 strip compute

        // v2 of this thread at byte tx*16 + 16 within its tap-row.
        const uint32_t lbase = sbase + (uint32_t)(tyw * SROWB + tx * 16 + 16);
        int s = 0;

        const int tid = ty * XQ + tx;
        const int L   = blockIdx.x * 10 + blockIdx.y;

        #pragma unroll 1
        for (int c = 0; c < CH_PER; c++) {
            asm volatile("cp.async.wait_group %0;" :: "n"(NSTG - 1));
            __syncwarp();

            const uint32_t lb = lbase + (uint32_t)(s * STAGEB);
            u64 accA = 0ull, accB = 0ull, accC = 0ull, accD = 0ull;
            #pragma unroll
            for (int i = 0; i < 5; i++) {
                const uint32_t ra = lb + (uint32_t)(i * SROWB);
                const float4 f25 = lds128(ra);        // v2 v3 v4 v5
                const float4 f69 = lds128(ra + 16);   // v6 v7 v8 v9
                const u64 P23 = pk2(f25.x, f25.y);
                const u64 P45 = pk2(f25.z, f25.w);
                const u64 P67 = pk2(f69.x, f69.y);
                const u64 P89 = pk2(f69.z, f69.w);
                const u64 P34 = pk2(f25.y, f25.z);
                const u64 P56 = pk2(f25.w, f69.x);
                const u64 P78 = pk2(f69.y, f69.z);
                const int t = i * 5;
                fma2(accA, P23, w01[t + 0]);
                fma2(accB, P34, w01[t + 1]);
                fma2(accA, P45, w01[t + 2]);
                fma2(accB, P56, w01[t + 3]);
                fma2(accA, P67, w01[t + 4]);
                fma2(accC, P45, w23[t + 0]);
                fma2(accD, P56, w23[t + 1]);
                fma2(accC, P67, w23[t + 2]);
                fma2(accD, P78, w23[t + 3]);
                fma2(accC, P89, w23[t + 4]);
            }
            const u64 s01 = add2(accA, accB);
            float2 o01;
            up2(s01, o01.x, o01.y);
            *reinterpret_cast<float2*>(ob) = o01;            // px x0, x0+1
            if (!phantom) {
                const u64 s23 = add2(accC, accD);
                float2 o23;
                up2(s23, o23.x, o23.y);
                *reinterpret_cast<float2*>(ob + 2) = o23;    // px x0+2, x0+3
            }
            ob += HW;

            // Prefetch channel c+NSTG into the stage just consumed.
            // Safe WAR: in-order warp issue means the FMAs consuming this stage's
            // LDS data issued (operands ready) before these LDGSTS issue.
            if (c + NSTG < CH_PER) {
                const float* fc = fb + (size_t)(c + NSTG) * HW;
                const uint32_t so = (uint32_t)(s * STAGEB);
                cpa16(sof[0] + so, fc + gof[0]);
                cpa16(sof[1] + so, fc + gof[1]);
                if (have3) cpa16(sof[2] + so, fc + gof[2]);
            }
            asm volatile("cp.async.commit_group;");   // empty group ok near the tail

            s = (s == NSTG - 1) ? 0 : s + 1;

            // ---- In-loop strip work: pixels x in {0,1}. Two rounds, placed at
            // iters 10 and 20; each thread computes at most one output per round
            // for its own channel cc = tid&31 (latency hidden by the pipeline).
            if (c == 10 || c == 20) {
                const int yxl = (tid >> 5) + ((c == 20) ? 4 : 0);
                const int yxg = L * SYX + yxl;
                if (yxl < SYX && yxg < 2 * H) {
                    const int cc = c0 + (tid & 31);
                    const int ys = yxg >> 1, xs = yxg & 1;
                    const float* fs = fm + (size_t)(b * C + cc) * HW;
                    const float* wp = swt + yxl * KK;
                    float acc = 0.f;
                    #pragma unroll
                    for (int i = 0; i < 5; i++) {
                        const int yy = iclamp(ys + i - 2, 0, H - 1);
                        const float4 v = *reinterpret_cast<const float4*>(fs + yy * W);
                        const float vv[4] = {v.x, v.y, v.z, v.w};
                        #pragma unroll
                        for (int j = 0; j < 5; j++) {
                            const int col = iclamp(xs + j - 2, 0, 3);
                            acc += wp[i * 5 + j] * vv[col];
                        }
                    }
                    out[((size_t)(b * C + cc) * H + ys) * W + xs] = acc;
                }
            }
        }
    } else {
        // ---- Generic dilation path (correctness fallback; not the benched case).
        // Unshifted tiling covers ALL pixels (no strip needed for d != 1).
        const int x0 = (blockIdx.x * XQ + tx) * 4;
        float wq0[KK], wq1[KK], wq2[KK], wq3[KK];
        {
            const float* kb = kern + ((size_t)b * KK * H + y) * W + x0;
            #pragma unroll
            for (int t = 0; t < KK; t++) {
                const float4 wq =
                    *reinterpret_cast<const float4*>(kb + (size_t)(KK - 1 - t) * HW);
                wq0[t] = wq.x; wq1[t] = wq.y; wq2[t] = wq.z; wq3[t] = wq.w;
            }
        }
        #pragma unroll 1
        for (int c = 0; c < CH_PER; c++) {
            float a0 = 0.f, a1 = 0.f, a2 = 0.f, a3 = 0.f;
            const float* fc = fm + (size_t)((b * C + c0 + c) * H) * W;
            #pragma unroll
            for (int i = 0; i < 5; i++) {
                const int yy = y + (i - 2) * d;
                if (yy < 0 || yy >= H) continue;
                const float* rp = fc + yy * W;
                #pragma unroll
                for (int j = 0; j < 5; j++) {
                    const int t = i * 5 + j;
                    const int xb2 = x0 + (j - 2) * d;
                    a0 += wq0[t] * ((xb2     >= 0 && xb2     < W) ? rp[xb2    ] : 0.f);
                    a1 += wq1[t] * ((xb2 + 1 >= 0 && xb2 + 1 < W) ? rp[xb2 + 1] : 0.f);
                    a2 += wq2[t] * ((xb2 + 2 >= 0 && xb2 + 2 < W) ? rp[xb2 + 2] : 0.f);
                    a3 += wq3[t] * ((xb2 + 3 >= 0 && xb2 + 3 < W) ? rp[xb2 + 3] : 0.f);
                }
            }
            float* op = out + (size_t)((b * C + c0 + c) * H + y) * W + x0;
            op[0] = a0; op[1] = a1; op[2] = a2; op[3] = a3;
        }
    }
}

extern "C" void kernel_launch(void* const* d_in, const int* in_sizes, int n_in,
                              void* d_out, int out_size) {
    const float* fm   = (const float*)d_in[0];
    const float* kern = (const float*)d_in[1];
    const int*   dil  = (n_in > 2) ? (const int*)d_in[2] : nullptr;
    float*       out  = (float*)d_out;

    dim3 blk(XQ, YB, 1);                          // 128 threads, 4 warps
    dim3 grd(W / 4 / XQ, H / YB, BS * CH_SPLIT);  // (5, 10, 8) = 400 blocks, 1 wave
    kconv_kernel<<<grd, blk>>>(fm, kern, dil, out);
}

// round 17
// speedup vs baseline: 1.3921x; 1.3338x over previous
#include <cuda_runtime.h>
#include <cstdint>

// Problem constants (fixed shapes for this problem instance)
#define BS 4
#define C  64
#define H  160
#define W  160
#define HW (H * W)
#define KK 25          // 5x5 taps
#define CH_SPLIT 2
#define CH_PER (C / CH_SPLIT)   // 32 channels per block
#define XQ 8           // x-quads (of 4 px) per block -> 32 px span
#define YB 16          // rows per block (4 warps x 4 rows)
#define NSTG 4         // cp.async pipeline depth
#define SROW 40        // staged floats per row (x window: 32 + 8 halo)
#define SROWB (SROW * 4)      // 160 B
#define STAGEB (8 * SROWB)    // 1280 B per stage (8 rows)
#define NSLOT 80              // 16B copy slots per stage (8 rows x 10 quads)

typedef unsigned long long u64;

__device__ __forceinline__ u64 pk2(float lo, float hi) {
    u64 r; asm("mov.b64 %0, {%1, %2};" : "=l"(r) : "f"(lo), "f"(hi)); return r;
}
__device__ __forceinline__ void up2(u64 v, float &lo, float &hi) {
    asm("mov.b64 {%0, %1}, %2;" : "=f"(lo), "=f"(hi) : "l"(v));
}
__device__ __forceinline__ void fma2(u64 &acc, u64 a, u64 b) {
    asm("fma.rn.f32x2 %0, %1, %2, %0;" : "+l"(acc) : "l"(a), "l"(b));
}
__device__ __forceinline__ u64 add2(u64 a, u64 b) {
    u64 r; asm("add.rn.f32x2 %0, %1, %2;" : "=l"(r) : "l"(a), "l"(b)); return r;
}
__device__ __forceinline__ void cpa16(uint32_t s, const float* g) {
    asm volatile("cp.async.cg.shared.global [%0], [%1], 16;" :: "r"(s), "l"(g));
}
__device__ __forceinline__ float4 lds128(uint32_t a) {
    float4 v;
    asm("ld.shared.v4.f32 {%0,%1,%2,%3}, [%4];"
        : "=f"(v.x), "=f"(v.y), "=f"(v.z), "=f"(v.w) : "r"(a));
    return v;
}
__device__ __forceinline__ int iclamp(int v, int lo, int hi) {
    return v < lo ? lo : (v > hi ? hi : v);
}

__global__ void __launch_bounds__(XQ * YB, 3)
kconv_kernel(const float* __restrict__ fm, const float* __restrict__ kern,
             const int* __restrict__ dil, float* __restrict__ out)
{
    // 4 warps x 4 stages x 8 rows x 40 floats = 20480 B
    __shared__ __align__(16) float sbuf[4 * NSTG * 8 * SROW];

    const int tx = threadIdx.x;
    const int ty = threadIdx.y;
    const int x0 = (blockIdx.x * XQ + tx) * 4;
    const int y  = blockIdx.y * YB + ty;
    const int bz = blockIdx.z;
    const int b  = bz >> 1;
    const int c0 = (bz & 1) * CH_PER;
    const int d  = dil ? dil[0] : 1;

    // ---- Load this pixel-quad's 25 weight quads (flipped tap order) into registers.
    u64 w01[KK], w23[KK];
    {
        const float* kb = kern + ((size_t)b * KK * H + y) * W + x0;
        #pragma unroll
        for (int t = 0; t < KK; t++) {
            const float4 wq =
                *reinterpret_cast<const float4*>(kb + (size_t)(KK - 1 - t) * HW);
            w01[t] = pk2(wq.x, wq.y);
            w23[t] = pk2(wq.z, wq.w);
        }
    }

    if (d == 1) {
        // ---- Fold boundary handling into the weights ONCE per thread:
        // out-of-bounds taps get zero weight; staged addresses are clamped,
        // so garbage values are multiplied by zero.
        #pragma unroll
        for (int i = 0; i < 5; i++) {
            const int yy = y + i - 2;
            const bool rok = (yy >= 0) && (yy < H);
            #pragma unroll
            for (int j = 0; j < 5; j++) {
                float a0, a1, a2, a3;
                up2(w01[i * 5 + j], a0, a1);
                up2(w23[i * 5 + j], a2, a3);
                if (!rok || x0 + 0 + j - 2 < 0 || x0 + 0 + j - 2 >= W) a0 = 0.f;
                if (!rok || x0 + 1 + j - 2 < 0 || x0 + 1 + j - 2 >= W) a1 = 0.f;
                if (!rok || x0 + 2 + j - 2 < 0 || x0 + 2 + j - 2 >= W) a2 = 0.f;
                if (!rok || x0 + 3 + j - 2 < 0 || x0 + 3 + j - 2 >= W) a3 = 0.f;
                w01[i * 5 + j] = pk2(a0, a1);
                w23[i * 5 + j] = pk2(a2, a3);
            }
        }

        // ---- Per-warp cp.async staging (16B .cg, proven R11 scheme).
        // Warp w covers output rows yw0..yw0+3, x span xb..xb+31.
        // Staged: rows yw0-2..yw0+5 (clamped), cols xb-4..xb+35 (clamped).
        const int lane = tx + (ty & 3) * 8;    // == tid % 32
        const int w    = ty >> 2;
        const int tyw  = ty & 3;
        const int xb   = blockIdx.x * 32;
        const int yw0  = blockIdx.y * YB + w * 4;

        const uint32_t sbase =
            (uint32_t)__cvta_generic_to_shared(sbuf) + (uint32_t)(w * NSTG * STAGEB);

        // 80 float4 slots (8 rows x 10 quads); lane handles slots lane, +32, +64.
        int gof[3]; uint32_t sof[3];
        #pragma unroll
        for (int k = 0; k < 3; k++) {
            const int slot = lane + 32 * k;
            const int r  = (slot < NSLOT) ? slot / 10 : 0;
            const int q  = (slot < NSLOT) ? slot % 10 : 0;
            const int rg = iclamp(yw0 - 2 + r, 0, H - 1);
            const int cg = iclamp(xb - 4 + q * 4, 0, W - 4);
            gof[k] = rg * W + cg;
            sof[k] = sbase + (uint32_t)(r * SROWB + q * 16);
        }
        const bool have3 = (lane < NSLOT - 64);   // lane < 16

        const float* fb = fm  + (size_t)(b * C + c0) * HW;
        float*       ob = out + ((size_t)(b * C + c0) * H + y) * W + x0;

        // Prologue: prefetch channels 0..NSTG-1.
        #pragma unroll
        for (int p = 0; p < NSTG; p++) {
            const float* fc = fb + (size_t)p * HW;
            const uint32_t so = (uint32_t)(p * STAGEB);
            cpa16(sof[0] + so, fc + gof[0]);
            cpa16(sof[1] + so, fc + gof[1]);
            if (have3) cpa16(sof[2] + so, fc + gof[2]);
            asm volatile("cp.async.commit_group;");
        }

        const uint32_t lbase = sbase + (uint32_t)(tyw * SROWB + tx * 16);
        const float* fpre = fb + (size_t)NSTG * HW;   // sliding prefetch pointer
        int s = 0;

        #pragma unroll 1
        for (int c = 0; c < CH_PER; c++) {
            asm volatile("cp.async.wait_group %0;" :: "n"(NSTG - 1));
            __syncwarp();

            const uint32_t lb = lbase + (uint32_t)(s * STAGEB);
            u64 accA = 0ull, accB = 0ull, accC = 0ull, accD = 0ull;
            #pragma unroll
            for (int i = 0; i < 5; i++) {
                const uint32_t ra = lb + (uint32_t)(i * SROWB);
                // window v_k = fm[x0-4+k]; three conflict-free, aligned LDS.128
                // (same crossbar cycles as lds64/128/64 but zero replays):
                const float4 f03 = lds128(ra);        // v0 v1 v2 v3 (v0,v1 unused)
                const float4 f47 = lds128(ra + 16);   // v4 v5 v6 v7
                const float4 f8B = lds128(ra + 32);   // v8 v9 (v10,v11 unused)
                const u64 P23 = pk2(f03.z, f03.w);
                const u64 P45 = pk2(f47.x, f47.y);
                const u64 P67 = pk2(f47.z, f47.w);
                const u64 P89 = pk2(f8B.x, f8B.y);
                const u64 P34 = pk2(f03.w, f47.x);
                const u64 P56 = pk2(f47.y, f47.z);
                const u64 P78 = pk2(f47.w, f8B.x);
                const int t = i * 5;
                fma2(accA, P23, w01[t + 0]);
                fma2(accB, P34, w01[t + 1]);
                fma2(accA, P45, w01[t + 2]);
                fma2(accB, P56, w01[t + 3]);
                fma2(accA, P67, w01[t + 4]);
                fma2(accC, P45, w23[t + 0]);
                fma2(accD, P56, w23[t + 1]);
                fma2(accC, P67, w23[t + 2]);
                fma2(accD, P78, w23[t + 3]);
                fma2(accC, P89, w23[t + 4]);
            }
            const u64 s01 = add2(accA, accB);
            const u64 s23 = add2(accC, accD);
            float4 o;
            up2(s01, o.x, o.y);
            up2(s23, o.z, o.w);
            *reinterpret_cast<float4*>(ob) = o;
            ob += HW;

            // Prefetch channel c+NSTG into the stage just consumed.
            // Safe WAR: in-order warp issue means the FMAs consuming this stage's
            // LDS data issued (operands ready) before these LDGSTS issue.
            if (c + NSTG < CH_PER) {
                const uint32_t so = (uint32_t)(s * STAGEB);
                cpa16(sof[0] + so, fpre + gof[0]);
                cpa16(sof[1] + so, fpre + gof[1]);
                if (have3) cpa16(sof[2] + so, fpre + gof[2]);
            }
            asm volatile("cp.async.commit_group;");   // empty group ok near the tail
            fpre += HW;

            s = (s == NSTG - 1) ? 0 : s + 1;
        }
    } else {
        // ---- Generic dilation path (correctness fallback; not the benched case) ----
        #pragma unroll 1
        for (int c = 0; c < CH_PER; c++) {
            float a0 = 0.f, a1 = 0.f, a2 = 0.f, a3 = 0.f;
            const float* fc = fm + (size_t)((b * C + c0 + c) * H) * W;
            #pragma unroll
            for (int i = 0; i < 5; i++) {
                const int yy = y + (i - 2) * d;
                if (yy < 0 || yy >= H) continue;
                const float* rp = fc + yy * W;
                #pragma unroll
                for (int j = 0; j < 5; j++) {
                    float wlo, whi, wl2, wh2;
                    up2(w01[i * 5 + j], wlo, whi);
                    up2(w23[i * 5 + j], wl2, wh2);
                    const int xb2 = x0 + (j - 2) * d;
                    a0 += wlo * ((xb2     >= 0 && xb2     < W) ? rp[xb2    ] : 0.f);
                    a1 += whi * ((xb2 + 1 >= 0 && xb2 + 1 < W) ? rp[xb2 + 1] : 0.f);
                    a2 += wl2 * ((xb2 + 2 >= 0 && xb2 + 2 < W) ? rp[xb2 + 2] : 0.f);
                    a3 += wh2 * ((xb2 + 3 >= 0 && xb2 + 3 < W) ? rp[xb2 + 3] : 0.f);
                }
            }
            float* op = out + (size_t)((b * C + c0 + c) * H + y) * W + x0;
            op[0] = a0; op[1] = a1; op[2] = a2; op[3] = a3;
        }
    }
}

extern "C" void kernel_launch(void* const* d_in, const int* in_sizes, int n_in,
                              void* d_out, int out_size) {
    const float* fm   = (const float*)d_in[0];
    const float* kern = (const float*)d_in[1];
    const int*   dil  = (n_in > 2) ? (const int*)d_in[2] : nullptr;
    float*       out  = (float*)d_out;

    dim3 blk(XQ, YB, 1);                          // 128 threads, 4 warps
    dim3 grd(W / 4 / XQ, H / YB, BS * CH_SPLIT);  // (5, 10, 8) = 400 blocks, 1 wave
    kconv_kernel<<<grd, blk>>>(fm, kern, dil, out);
}